// round 5
// baseline (speedup 1.0000x reference)
#include <cuda_runtime.h>
#include <cstdint>

// ============================================================================
// MemristorLinear: out[B,OUT] = x[B,IN] @ W[OUT,IN]^T + bias,
//                  W[o,i] = values[w_idx[o,i]]
// B=8192, IN=4096, OUT=4096, NVAL=1024.
//
// tf32 mma.sync.m16n8k8 GEMM, CTA 128x256, warp 64x64, 3-stage cp.async.
// R5: scratch (g_X/g_W) stored with per-32k-block permutation
//     pos = (k%4)*8 + k/4  -> every fragment load is one LDS.128
//     (thread (lr,lc) needs k = lc+4t, t=0..7 -> contiguous after permute).
// ============================================================================

#define B_DIM   8192
#define IN_DIM  4096
#define OUT_DIM 4096

#define BM 128
#define BN 256
#define BK 32
#define STAGES 3
#define KITERS (IN_DIM / BK)     // 128
#define THREADS 256

#define LDSTRIDE 36                        // floats per smem row (32 + 4 pad)
#define A_FLOATS (BM * LDSTRIDE)           // 4608
#define B_FLOATS (BN * LDSTRIDE)           // 9216
#define STAGE_FLOATS (A_FLOATS + B_FLOATS) // 13824
#define SMEM_BYTES (STAGES * STAGE_FLOATS * 4)  // 165888

// Scratch (allocation-free rule: __device__ globals)
__device__ float g_W[(size_t)OUT_DIM * IN_DIM];   // 64 MB permuted tf32 W
__device__ float g_X[(size_t)B_DIM * IN_DIM];     // 128 MB permuted tf32 x
__device__ int   g_idx_is64;                      // w_idx dtype flag

// ---------------------------------------------------------------------------
// helpers
// ---------------------------------------------------------------------------
__device__ __forceinline__ uint32_t smem_u32(const void* p) {
    uint32_t a;
    asm("{ .reg .u64 t; cvta.to.shared.u64 t, %1; cvt.u32.u64 %0, t; }"
        : "=r"(a) : "l"(p));
    return a;
}

__device__ __forceinline__ void cp_async16(uint32_t s, const void* g) {
    asm volatile("cp.async.cg.shared.global [%0], [%1], 16;\n" :: "r"(s), "l"(g));
}

__device__ __forceinline__ uint32_t tf32_rna(float f) {
    uint32_t u;
    asm("cvt.rna.tf32.f32 %0, %1;" : "=r"(u) : "f"(f));
    return u;
}

// D += A*B : m16n8k8 tf32, row.col, fp32 accumulate
__device__ __forceinline__ void mma_tf32(float* c, uint32_t a0, uint32_t a1,
                                         uint32_t a2, uint32_t a3,
                                         uint32_t b0, uint32_t b1) {
    asm volatile(
        "mma.sync.aligned.m16n8k8.row.col.f32.tf32.tf32.f32 "
        "{%0,%1,%2,%3}, {%4,%5,%6,%7}, {%8,%9}, {%0,%1,%2,%3};"
        : "+f"(c[0]), "+f"(c[1]), "+f"(c[2]), "+f"(c[3])
        : "r"(a0), "r"(a1), "r"(a2), "r"(a3), "r"(b0), "r"(b1));
}

// ---------------------------------------------------------------------------
// Pre-pass 0: detect w_idx dtype (indices < 1024 -> int64 odd words all 0)
// ---------------------------------------------------------------------------
__global__ void mml_detect_idx(const int* __restrict__ w32) {
    int nz = 0;
    #pragma unroll
    for (int i = 0; i < 64; i++) nz |= w32[2 * i + 1];
    g_idx_is64 = (nz == 0) ? 1 : 0;
}

// ---------------------------------------------------------------------------
// Pre-pass 1: round x to tf32, store k-permuted into g_X.
// Thread t handles elements k0=4t..4t+3. Destination within the 32-block:
// pos(k) = (k%4)*8 + (k%32)/4  ->  dst = 32*(t>>3) + (t&7) + i*8.
// ---------------------------------------------------------------------------
__global__ void mml_round_x(const float4* __restrict__ x, int n4) {
    int t = blockIdx.x * blockDim.x + threadIdx.x;
    if (t < n4) {
        float4 v = x[t];
        float* dst = g_X + 32 * (size_t)(t >> 3) + (t & 7);
        dst[0]  = __uint_as_float(tf32_rna(v.x));
        dst[8]  = __uint_as_float(tf32_rna(v.y));
        dst[16] = __uint_as_float(tf32_rna(v.z));
        dst[24] = __uint_as_float(tf32_rna(v.w));
    }
}

// ---------------------------------------------------------------------------
// Pre-pass 2: gather W from codebook (int32 OR int64 idx), tf32-round,
// store k-permuted into g_W (same permutation as g_X).
// ---------------------------------------------------------------------------
__global__ void mml_gather_w(const float* __restrict__ values,
                             const void* __restrict__ widx, int n4) {
    int t = blockIdx.x * blockDim.x + threadIdx.x;
    if (t >= n4) return;
    int i0, i1, i2, i3;
    if (g_idx_is64) {
        const longlong2* p = reinterpret_cast<const longlong2*>(widx) + 2 * t;
        longlong2 a = p[0];
        longlong2 b = p[1];
        i0 = (int)a.x; i1 = (int)a.y; i2 = (int)b.x; i3 = (int)b.y;
    } else {
        int4 a = reinterpret_cast<const int4*>(widx)[t];
        i0 = a.x; i1 = a.y; i2 = a.z; i3 = a.w;
    }
    float* dst = g_W + 32 * (size_t)(t >> 3) + (t & 7);
    dst[0]  = __uint_as_float(tf32_rna(__ldg(values + i0)));
    dst[8]  = __uint_as_float(tf32_rna(__ldg(values + i1)));
    dst[16] = __uint_as_float(tf32_rna(__ldg(values + i2)));
    dst[24] = __uint_as_float(tf32_rna(__ldg(values + i3)));
}

// ---------------------------------------------------------------------------
// Main GEMM: 128x256 CTA tile, 8 warps (2 M x 4 N), 64x64 warp tiles.
// Fragment loads are LDS.128 on the permuted layout:
//   float4 at row*36 + lc*8 + 4h holds this thread's k=lc+4t, t=4h..4h+3,
//   i.e. kk=2h   : k0 -> .x, k0+4 -> .y
//        kk=2h+1 : k0 -> .z, k0+4 -> .w
// ---------------------------------------------------------------------------
__global__ __launch_bounds__(THREADS, 1)
void mml_gemm(const float* __restrict__ bias, float* __restrict__ out) {
    extern __shared__ float sm[];
    const int tid  = threadIdx.x;
    const int lane = tid & 31;
    const int wid  = tid >> 5;
    const int wm   = wid & 1;        // 2 warps in M
    const int wn   = wid >> 1;       // 4 warps in N
    const int m0   = blockIdx.y * BM;
    const int n0   = blockIdx.x * BN;

    const uint32_t smem_base = smem_u32(sm);
    const int lr = lane >> 2;        // 0..7
    const int lc = lane & 3;         // 0..3

    // accumulators: 4 m-tiles x 8 n-tiles x 4 regs = 128
    float c[4][8][4];
    #pragma unroll
    for (int mt = 0; mt < 4; mt++)
        #pragma unroll
        for (int nt = 0; nt < 8; nt++)
            #pragma unroll
            for (int r = 0; r < 4; r++) c[mt][nt][r] = 0.0f;

    auto load_stage = [&](int ks, int slot) {
        uint32_t sa = smem_base + (uint32_t)(slot * STAGE_FLOATS * 4);
        uint32_t sb = sa + A_FLOATS * 4;
        const float* ag = g_X + (size_t)m0 * IN_DIM + (size_t)ks * BK;
        const float* bg = g_W + (size_t)n0 * IN_DIM + (size_t)ks * BK;
        #pragma unroll
        for (int q = tid; q < BM * 8; q += THREADS) {
            int row = q >> 3, kc = q & 7;
            cp_async16(sa + (uint32_t)(row * LDSTRIDE + kc * 4) * 4,
                       ag + (size_t)row * IN_DIM + kc * 4);
        }
        #pragma unroll
        for (int q = tid; q < BN * 8; q += THREADS) {
            int row = q >> 3, kc = q & 7;
            cp_async16(sb + (uint32_t)(row * LDSTRIDE + kc * 4) * 4,
                       bg + (size_t)row * IN_DIM + kc * 4);
        }
    };

    load_stage(0, 0);
    asm volatile("cp.async.commit_group;" ::: "memory");
    load_stage(1, 1);
    asm volatile("cp.async.commit_group;" ::: "memory");

    const int frag_off = lc * 8;     // per-thread float offset within a row

    for (int i = 0; i < KITERS; i++) {
        asm volatile("cp.async.wait_group 1;" ::: "memory");
        __syncthreads();

        if (i + 2 < KITERS) load_stage(i + 2, (i + 2) % STAGES);
        asm volatile("cp.async.commit_group;" ::: "memory");

        const float* sA = sm + (i % STAGES) * STAGE_FLOATS;
        const float* sB = sA + A_FLOATS;

        #pragma unroll
        for (int h = 0; h < 2; h++) {           // kk pairs (2h, 2h+1)
            const int fo = frag_off + 4 * h;
            // A fragments for all 4 m-tiles: 8 x LDS.128
            float4 va0[4], va1[4];
            #pragma unroll
            for (int mt = 0; mt < 4; mt++) {
                int row = wm * 64 + mt * 16 + lr;
                va0[mt] = *reinterpret_cast<const float4*>(sA + row * LDSTRIDE + fo);
                va1[mt] = *reinterpret_cast<const float4*>(sA + (row + 8) * LDSTRIDE + fo);
            }
            // B row-vectors, 8 MMAs each (4 mt x 2 kk)
            #pragma unroll
            for (int nt = 0; nt < 8; nt++) {
                int nrow = wn * 64 + nt * 8 + lr;
                float4 vb = *reinterpret_cast<const float4*>(sB + nrow * LDSTRIDE + fo);
                #pragma unroll
                for (int mt = 0; mt < 4; mt++) {
                    mma_tf32(c[mt][nt],
                             __float_as_uint(va0[mt].x), __float_as_uint(va1[mt].x),
                             __float_as_uint(va0[mt].y), __float_as_uint(va1[mt].y),
                             __float_as_uint(vb.x), __float_as_uint(vb.y));
                    mma_tf32(c[mt][nt],
                             __float_as_uint(va0[mt].z), __float_as_uint(va1[mt].z),
                             __float_as_uint(va0[mt].w), __float_as_uint(va1[mt].w),
                             __float_as_uint(vb.z), __float_as_uint(vb.w));
                }
            }
        }
    }

    // ---- epilogue: add bias, write float2 coalesced ----
    float2 bb[8];
    #pragma unroll
    for (int nt = 0; nt < 8; nt++) {
        int cn = n0 + wn * 64 + nt * 8 + lc * 2;
        bb[nt].x = __ldg(bias + cn);
        bb[nt].y = __ldg(bias + cn + 1);
    }
    #pragma unroll
    for (int mt = 0; mt < 4; mt++) {
        int r0 = m0 + wm * 64 + mt * 16 + lr;
        int r1 = r0 + 8;
        float* o0 = out + (size_t)r0 * OUT_DIM;
        float* o1 = out + (size_t)r1 * OUT_DIM;
        #pragma unroll
        for (int nt = 0; nt < 8; nt++) {
            int cn = n0 + wn * 64 + nt * 8 + lc * 2;
            float2 v0, v1;
            v0.x = c[mt][nt][0] + bb[nt].x;
            v0.y = c[mt][nt][1] + bb[nt].y;
            v1.x = c[mt][nt][2] + bb[nt].x;
            v1.y = c[mt][nt][3] + bb[nt].y;
            *reinterpret_cast<float2*>(o0 + cn) = v0;
            *reinterpret_cast<float2*>(o1 + cn) = v1;
        }
    }
}

// ---------------------------------------------------------------------------
// kernel_launch — inputs identified by element count (order-proof):
//   x: 33554432, values: 1024, bias: 4096, w_idx: 16777216
// ---------------------------------------------------------------------------
extern "C" void kernel_launch(void* const* d_in, const int* in_sizes, int n_in,
                              void* d_out, int out_size) {
    const float* x      = nullptr;
    const float* values = nullptr;
    const float* bias   = nullptr;
    const void*  widx   = nullptr;

    for (int i = 0; i < n_in; i++) {
        switch (in_sizes[i]) {
            case 33554432: x      = (const float*)d_in[i]; break;
            case 1024:     values = (const float*)d_in[i]; break;
            case 4096:     bias   = (const float*)d_in[i]; break;
            case 16777216: widx   = d_in[i];               break;
            default: break;
        }
    }
    float* out = (float*)d_out;

    int nx4 = (B_DIM * IN_DIM) / 4;        // 8388608
    int nw4 = (OUT_DIM * IN_DIM) / 4;      // 4194304

    mml_detect_idx<<<1, 1>>>((const int*)widx);
    mml_round_x<<<nx4 / 256, 256>>>((const float4*)x, nx4);
    mml_gather_w<<<nw4 / 256, 256>>>(values, widx, nw4);

    cudaFuncSetAttribute(mml_gemm, cudaFuncAttributeMaxDynamicSharedMemorySize,
                         SMEM_BYTES);
    dim3 grid(OUT_DIM / BN, B_DIM / BM);   // (16, 64)
    mml_gemm<<<grid, THREADS, SMEM_BYTES>>>(bias, out);
}

// round 6
// speedup vs baseline: 1.5072x; 1.5072x over previous
#include <cuda_runtime.h>
#include <cstdint>

// ============================================================================
// MemristorLinear: out[B,OUT] = x[B,IN] @ W[OUT,IN]^T + bias,
//                  W[o,i] = values[w_idx[o,i]]
// B=8192, IN=4096, OUT=4096, NVAL=1024.
//
// tf32 mma.sync.m16n8k8 GEMM. R6: revert to R4's scalar-LDS fragment loads
// (ptxas-friendly); CTA tile 128x128 with 4 warps (64x64 warp tiles) and
// __launch_bounds__(128,2) -> 2 CTAs/SM so one CTA's MMAs cover the other's
// barrier + cp.async phases.
// ============================================================================

#define B_DIM   8192
#define IN_DIM  4096
#define OUT_DIM 4096

#define BM 128
#define BN 128
#define BK 32
#define STAGES 3
#define KITERS (IN_DIM / BK)     // 128
#define THREADS 128

#define LDSTRIDE 36                        // floats per smem row (32 + 4 pad)
#define A_FLOATS (BM * LDSTRIDE)           // 4608
#define B_FLOATS (BN * LDSTRIDE)           // 4608
#define STAGE_FLOATS (A_FLOATS + B_FLOATS) // 9216
#define SMEM_BYTES (STAGES * STAGE_FLOATS * 4)  // 110592 (108 KB -> 2 CTAs/SM)

// Scratch (allocation-free rule: __device__ globals)
__device__ float g_W[(size_t)OUT_DIM * IN_DIM];   // 64 MB tf32-rounded gathered W
__device__ float g_X[(size_t)B_DIM * IN_DIM];     // 128 MB tf32-rounded x
__device__ int   g_idx_is64;                      // w_idx dtype flag

// ---------------------------------------------------------------------------
// helpers
// ---------------------------------------------------------------------------
__device__ __forceinline__ uint32_t smem_u32(const void* p) {
    uint32_t a;
    asm("{ .reg .u64 t; cvta.to.shared.u64 t, %1; cvt.u32.u64 %0, t; }"
        : "=r"(a) : "l"(p));
    return a;
}

__device__ __forceinline__ void cp_async16(uint32_t s, const void* g) {
    asm volatile("cp.async.cg.shared.global [%0], [%1], 16;\n" :: "r"(s), "l"(g));
}

__device__ __forceinline__ uint32_t tf32_rna(float f) {
    uint32_t u;
    asm("cvt.rna.tf32.f32 %0, %1;" : "=r"(u) : "f"(f));
    return u;
}

// D += A*B : m16n8k8 tf32, row.col, fp32 accumulate
__device__ __forceinline__ void mma_tf32(float* c, const uint32_t* a,
                                         const uint32_t* b) {
    asm volatile(
        "mma.sync.aligned.m16n8k8.row.col.f32.tf32.tf32.f32 "
        "{%0,%1,%2,%3}, {%4,%5,%6,%7}, {%8,%9}, {%0,%1,%2,%3};"
        : "+f"(c[0]), "+f"(c[1]), "+f"(c[2]), "+f"(c[3])
        : "r"(a[0]), "r"(a[1]), "r"(a[2]), "r"(a[3]), "r"(b[0]), "r"(b[1]));
}

// ---------------------------------------------------------------------------
// Pre-pass 0: detect w_idx dtype (indices < 1024 -> int64 odd words all 0)
// ---------------------------------------------------------------------------
__global__ void mml_detect_idx(const int* __restrict__ w32) {
    int nz = 0;
    #pragma unroll
    for (int i = 0; i < 64; i++) nz |= w32[2 * i + 1];
    g_idx_is64 = (nz == 0) ? 1 : 0;
}

// ---------------------------------------------------------------------------
// Pre-pass 1: round x to tf32 into g_X (plain row-major layout)
// ---------------------------------------------------------------------------
__global__ void mml_round_x(const float4* __restrict__ x, int n4) {
    int t = blockIdx.x * blockDim.x + threadIdx.x;
    if (t < n4) {
        float4 v = x[t];
        uint4 o;
        o.x = tf32_rna(v.x); o.y = tf32_rna(v.y);
        o.z = tf32_rna(v.z); o.w = tf32_rna(v.w);
        reinterpret_cast<uint4*>(g_X)[t] = o;
    }
}

// ---------------------------------------------------------------------------
// Pre-pass 2: gather W from codebook (int32 OR int64 idx), tf32-round to g_W
// ---------------------------------------------------------------------------
__global__ void mml_gather_w(const float* __restrict__ values,
                             const void* __restrict__ widx, int n4) {
    int t = blockIdx.x * blockDim.x + threadIdx.x;
    if (t >= n4) return;
    int i0, i1, i2, i3;
    if (g_idx_is64) {
        const longlong2* p = reinterpret_cast<const longlong2*>(widx) + 2 * t;
        longlong2 a = p[0];
        longlong2 b = p[1];
        i0 = (int)a.x; i1 = (int)a.y; i2 = (int)b.x; i3 = (int)b.y;
    } else {
        int4 a = reinterpret_cast<const int4*>(widx)[t];
        i0 = a.x; i1 = a.y; i2 = a.z; i3 = a.w;
    }
    uint4 o;
    o.x = tf32_rna(__ldg(values + i0));
    o.y = tf32_rna(__ldg(values + i1));
    o.z = tf32_rna(__ldg(values + i2));
    o.w = tf32_rna(__ldg(values + i3));
    reinterpret_cast<uint4*>(g_W)[t] = o;
}

// ---------------------------------------------------------------------------
// Main GEMM: 128x128 CTA tile, 4 warps (2 M x 2 N), 64x64 warp tiles,
// 2 CTAs per SM.
// ---------------------------------------------------------------------------
__global__ __launch_bounds__(THREADS, 2)
void mml_gemm(const float* __restrict__ bias, float* __restrict__ out) {
    extern __shared__ float sm[];
    const int tid  = threadIdx.x;
    const int lane = tid & 31;
    const int wid  = tid >> 5;
    const int wm   = wid & 1;        // 2 warps in M
    const int wn   = wid >> 1;       // 2 warps in N
    const int m0   = blockIdx.y * BM;
    const int n0   = blockIdx.x * BN;

    const uint32_t smem_base = smem_u32(sm);
    const int lr = lane >> 2;        // 0..7
    const int lc = lane & 3;         // 0..3

    // accumulators: 4 m-tiles x 8 n-tiles x 4 regs = 128
    float c[4][8][4];
    #pragma unroll
    for (int mt = 0; mt < 4; mt++)
        #pragma unroll
        for (int nt = 0; nt < 8; nt++)
            #pragma unroll
            for (int r = 0; r < 4; r++) c[mt][nt][r] = 0.0f;

    // ---- stage loader: A (BMxBK) + B (BNxBK) via cp.async, padded rows ----
    auto load_stage = [&](int ks, int slot) {
        uint32_t sa = smem_base + (uint32_t)(slot * STAGE_FLOATS * 4);
        uint32_t sb = sa + A_FLOATS * 4;
        const float* ag = g_X + (size_t)m0 * IN_DIM + (size_t)ks * BK;
        const float* bg = g_W + (size_t)n0 * IN_DIM + (size_t)ks * BK;
        #pragma unroll
        for (int q = tid; q < BM * 8; q += THREADS) {
            int row = q >> 3, kc = q & 7;
            cp_async16(sa + (uint32_t)(row * LDSTRIDE + kc * 4) * 4,
                       ag + (size_t)row * IN_DIM + kc * 4);
        }
        #pragma unroll
        for (int q = tid; q < BN * 8; q += THREADS) {
            int row = q >> 3, kc = q & 7;
            cp_async16(sb + (uint32_t)(row * LDSTRIDE + kc * 4) * 4,
                       bg + (size_t)row * IN_DIM + kc * 4);
        }
    };

    load_stage(0, 0);
    asm volatile("cp.async.commit_group;" ::: "memory");
    load_stage(1, 1);
    asm volatile("cp.async.commit_group;" ::: "memory");

    for (int i = 0; i < KITERS; i++) {
        asm volatile("cp.async.wait_group 1;" ::: "memory");
        __syncthreads();

        if (i + 2 < KITERS) load_stage(i + 2, (i + 2) % STAGES);
        asm volatile("cp.async.commit_group;" ::: "memory");

        const float* sA = sm + (i % STAGES) * STAGE_FLOATS;
        const float* sB = sA + A_FLOATS;

        #pragma unroll
        for (int kk = 0; kk < 4; kk++) {
            const int k0 = kk * 8 + lc;
            uint32_t af[4][4], bf[8][2];
            #pragma unroll
            for (int mt = 0; mt < 4; mt++) {
                int row = wm * 64 + mt * 16 + lr;
                const uint32_t* p0 = (const uint32_t*)(sA + row * LDSTRIDE);
                const uint32_t* p1 = (const uint32_t*)(sA + (row + 8) * LDSTRIDE);
                af[mt][0] = p0[k0];
                af[mt][1] = p1[k0];
                af[mt][2] = p0[k0 + 4];
                af[mt][3] = p1[k0 + 4];
            }
            #pragma unroll
            for (int nt = 0; nt < 8; nt++) {
                int nrow = wn * 64 + nt * 8 + lr;
                const uint32_t* p = (const uint32_t*)(sB + nrow * LDSTRIDE);
                bf[nt][0] = p[k0];
                bf[nt][1] = p[k0 + 4];
            }
            #pragma unroll
            for (int mt = 0; mt < 4; mt++)
                #pragma unroll
                for (int nt = 0; nt < 8; nt++)
                    mma_tf32(c[mt][nt], af[mt], bf[nt]);
        }
    }

    // ---- epilogue: add bias, write float2 coalesced ----
    float2 bb[8];
    #pragma unroll
    for (int nt = 0; nt < 8; nt++) {
        int cn = n0 + wn * 64 + nt * 8 + lc * 2;
        bb[nt].x = __ldg(bias + cn);
        bb[nt].y = __ldg(bias + cn + 1);
    }
    #pragma unroll
    for (int mt = 0; mt < 4; mt++) {
        int r0 = m0 + wm * 64 + mt * 16 + lr;
        int r1 = r0 + 8;
        float* o0 = out + (size_t)r0 * OUT_DIM;
        float* o1 = out + (size_t)r1 * OUT_DIM;
        #pragma unroll
        for (int nt = 0; nt < 8; nt++) {
            int cn = n0 + wn * 64 + nt * 8 + lc * 2;
            float2 v0, v1;
            v0.x = c[mt][nt][0] + bb[nt].x;
            v0.y = c[mt][nt][1] + bb[nt].y;
            v1.x = c[mt][nt][2] + bb[nt].x;
            v1.y = c[mt][nt][3] + bb[nt].y;
            *reinterpret_cast<float2*>(o0 + cn) = v0;
            *reinterpret_cast<float2*>(o1 + cn) = v1;
        }
    }
}

// ---------------------------------------------------------------------------
// kernel_launch — inputs identified by element count (order-proof):
//   x: 33554432, values: 1024, bias: 4096, w_idx: 16777216
// ---------------------------------------------------------------------------
extern "C" void kernel_launch(void* const* d_in, const int* in_sizes, int n_in,
                              void* d_out, int out_size) {
    const float* x      = nullptr;
    const float* values = nullptr;
    const float* bias   = nullptr;
    const void*  widx   = nullptr;

    for (int i = 0; i < n_in; i++) {
        switch (in_sizes[i]) {
            case 33554432: x      = (const float*)d_in[i]; break;
            case 1024:     values = (const float*)d_in[i]; break;
            case 4096:     bias   = (const float*)d_in[i]; break;
            case 16777216: widx   = d_in[i];               break;
            default: break;
        }
    }
    float* out = (float*)d_out;

    int nx4 = (B_DIM * IN_DIM) / 4;        // 8388608
    int nw4 = (OUT_DIM * IN_DIM) / 4;      // 4194304

    mml_detect_idx<<<1, 1>>>((const int*)widx);
    mml_round_x<<<nx4 / 256, 256>>>((const float4*)x, nx4);
    mml_gather_w<<<nw4 / 256, 256>>>(values, widx, nw4);

    cudaFuncSetAttribute(mml_gemm, cudaFuncAttributeMaxDynamicSharedMemorySize,
                         SMEM_BYTES);
    dim3 grid(OUT_DIM / BN, B_DIM / BM);   // (32, 64)
    mml_gemm<<<grid, THREADS, SMEM_BYTES>>>(bias, out);
}